// round 7
// baseline (speedup 1.0000x reference)
#include <cuda_runtime.h>
#include <cuda_bf16.h>
#include <cstdint>

#define N_DIM   16384
#define F_DIM   32
#define BM      128
#define BK      32
#define THREADS 256
#define GRID    296
#define KCHUNKS 16
#define UNIT_STAGES 32                     // stages per unit (BK floats each)
#define TOTAL_UNITS (128 * KCHUNKS)        // 2048
#define ROWB    80                         // B bf16 smem row stride (64B + 16 pad)

// ---- smem stage layout ----
#define STAGE_A_SZ 16384                   // 128 rows x 32 f32 (128B/row, swizzled)
#define BH_SZ      2560                    // 32 rows x 80B
#define STAGE_SZ   (STAGE_A_SZ + 2 * BH_SZ)   // 21504
#define NSTAGE     5
#define SMEM_TOTAL (NSTAGE * STAGE_SZ)     // 107520  -> 2 CTAs/SM

// pre-split B operands (bf16 hi/lo), [F_DIM][N_DIM]
__device__ __align__(16) __nv_bfloat16 g_bh1[F_DIM * N_DIM];
__device__ __align__(16) __nv_bfloat16 g_bl1[F_DIM * N_DIM];
__device__ __align__(16) __nv_bfloat16 g_bh2[F_DIM * N_DIM];
__device__ __align__(16) __nv_bfloat16 g_bl2[F_DIM * N_DIM];
// K-split partials: [kc][row][col] f32  (16 * 16384 * 32 * 4B = 32 MB)
__device__ __align__(16) float g_part[KCHUNKS * N_DIM * F_DIM];

// ---------------- helpers ----------------
__device__ __forceinline__ uint32_t smem_u32(const void* p) {
    uint32_t a;
    asm("{ .reg .u64 t; cvta.to.shared.u64 t, %1; cvt.u32.u64 %0, t; }" : "=r"(a) : "l"(p));
    return a;
}
#define CP_ASYNC16(dst, src) \
    asm volatile("cp.async.cg.shared.global [%0], [%1], 16;" :: "r"(dst), "l"(src) : "memory")
#define CP_COMMIT()  asm volatile("cp.async.commit_group;" ::: "memory")
#define CP_WAIT3()   asm volatile("cp.async.wait_group 3;" ::: "memory")

__device__ __forceinline__ float2 lds_f2(uint32_t a) {
    float2 v;
    asm volatile("ld.shared.v2.f32 {%0,%1}, [%2];" : "=f"(v.x), "=f"(v.y) : "r"(a));
    return v;
}
__device__ __forceinline__ uint32_t lds32(uint32_t addr) {
    uint32_t v;
    asm volatile("ld.shared.b32 %0, [%1];" : "=r"(v) : "r"(addr));
    return v;
}
__device__ __forceinline__ void mma_bf16(float* c, const uint32_t* a, uint32_t b0, uint32_t b1) {
    asm volatile("mma.sync.aligned.m16n8k16.row.col.f32.bf16.bf16.f32 "
                 "{%0,%1,%2,%3}, {%4,%5,%6,%7}, {%8,%9}, {%0,%1,%2,%3};"
                 : "+f"(c[0]), "+f"(c[1]), "+f"(c[2]), "+f"(c[3])
                 : "r"(a[0]), "r"(a[1]), "r"(a[2]), "r"(a[3]), "r"(b0), "r"(b1));
}
__device__ __forceinline__ uint32_t pack_bf16_rn(float lo, float hi) {
    uint32_t r;
    asm("cvt.rn.bf16x2.f32 %0, %1, %2;" : "=r"(r) : "f"(hi), "f"(lo));
    return r;
}
__device__ __forceinline__ uint32_t split2(float2 v, uint32_t& lo) {
    uint32_t hx = (__float_as_uint(v.x) + 0x8000u) & 0xFFFF0000u;
    uint32_t hy = (__float_as_uint(v.y) + 0x8000u) & 0xFFFF0000u;
    lo = pack_bf16_rn(v.x - __uint_as_float(hx), v.y - __uint_as_float(hy));
    return __byte_perm(hx, hy, 0x7632);
}
__device__ __forceinline__ void split_g(float v, __nv_bfloat16* ph, __nv_bfloat16* pl) {
    __nv_bfloat16 h = __float2bfloat16(v);
    *ph = h;
    *pl = __float2bfloat16(v - __bfloat162float(h));
}

// ---------- prep: split((features @ W)^T) -> g_bh1/g_bl1 ----------
__global__ void feat_w_kernel(const float* __restrict__ feat,
                              const float* __restrict__ W) {
    __shared__ float sW[F_DIM * F_DIM];
    int tid = threadIdx.x;
    for (int i = tid; i < F_DIM * F_DIM; i += 128) sW[i] = W[i];
    __syncthreads();
    int row = blockIdx.x * 128 + tid;
    float f[F_DIM];
    const float4* fr = reinterpret_cast<const float4*>(feat + (size_t)row * F_DIM);
#pragma unroll
    for (int i = 0; i < 8; i++) {
        float4 v = fr[i];
        f[4*i] = v.x; f[4*i+1] = v.y; f[4*i+2] = v.z; f[4*i+3] = v.w;
    }
#pragma unroll 4
    for (int c = 0; c < F_DIM; c++) {
        float acc = 0.f;
#pragma unroll
        for (int k = 0; k < F_DIM; k++) acc = fmaf(f[k], sW[k * F_DIM + c], acc);
        split_g(acc, &g_bh1[(size_t)c * N_DIM + row], &g_bl1[(size_t)c * N_DIM + row]);
    }
}

// ---------- persistent big GEMM: partials over K-chunks ----------
template <int MODE>
__global__ __launch_bounds__(THREADS, 2)
void big_gemm_mma(const float* __restrict__ A) {
    const __nv_bfloat16* __restrict__ Bh = (MODE == 1) ? g_bh1 : g_bh2;
    const __nv_bfloat16* __restrict__ Bl = (MODE == 1) ? g_bl1 : g_bl2;

    extern __shared__ char smem[];
    const uint32_t sb = smem_u32(smem);
    const int tid  = threadIdx.x;
    const int lane = tid & 31;
    const int w    = tid >> 5;

    const int u0 = (blockIdx.x * TOTAL_UNITS) / GRID;
    const int u1 = ((blockIdx.x + 1) * TOTAL_UNITS) / GRID;
    const int S0 = u0 * UNIT_STAGES;
    const int S1 = u1 * UNIT_STAGES;

    // ---- producer slots ----
    // A: 4 chunks of 16B; chunk = tid + 256*i -> row = chunk>>3, granule g = chunk&7
    int arow[4]; int agr[4]; uint32_t adst[4];
#pragma unroll
    for (int i = 0; i < 4; i++) {
        int chunk = tid + THREADS * i;
        arow[i] = chunk >> 3;  agr[i] = chunk & 7;
        adst[i] = (uint32_t)(arow[i] * 128 + ((agr[i] ^ (arow[i] & 7)) << 4));
    }
    // B: 1 chunk; tid<128 -> bh, tid>=128 -> bl; n = (tid&127)>>2, g = (tid&127)&3
    const int bn = (tid & 127) >> 2, bg = (tid & 127) & 3;
    const __nv_bfloat16* bsrc = ((tid < 128) ? Bh : Bl) + (size_t)bn * N_DIM + bg * 8;
    const uint32_t bdst = (uint32_t)(STAGE_A_SZ + ((tid < 128) ? 0 : BH_SZ) + bn * ROWB + bg * 16);

    auto issue = [&](int s) {
        const int u = s >> 5;
        const int m = u >> 4;
        const int kf = ((u & 15) * UNIT_STAGES + (s & 31)) * BK;   // absolute k (floats)
        const uint32_t stg = sb + (uint32_t)(s % NSTAGE) * STAGE_SZ;
        const float* abase = A + (size_t)(m * BM) * N_DIM + kf;
#pragma unroll
        for (int i = 0; i < 4; i++)
            CP_ASYNC16(stg + adst[i], abase + (size_t)arow[i] * N_DIM + agr[i] * 4);
        CP_ASYNC16(stg + bdst, bsrc + kf);
    };

    // ---- consumer addressing ----
    const int r1 = w * 16 + (lane >> 2);
    const uint32_t xr = (uint32_t)(r1 & 7);
    const uint32_t arow1 = (uint32_t)(r1 * 128);
    const uint32_t arow2 = arow1 + 8 * 128;
    const uint32_t gb  = (uint32_t)((lane & 3) >> 1);
    const uint32_t aib = (uint32_t)((lane & 1) * 8);
    const uint32_t boff = (uint32_t)(STAGE_A_SZ + (lane >> 2) * ROWB + (lane & 3) * 4);

    float acc[4][4];
#pragma unroll
    for (int j = 0; j < 4; j++)
#pragma unroll
        for (int i = 0; i < 4; i++) acc[j][i] = 0.f;

    issue(S0);     CP_COMMIT();
    issue(S0 + 1); CP_COMMIT();
    issue(S0 + 2); CP_COMMIT();
    issue(S0 + 3); CP_COMMIT();

    for (int s = S0; s < S1; s++) {
        CP_WAIT3();
        __syncthreads();
        if (s + 4 < S1) issue(s + 4);
        CP_COMMIT();

        const uint32_t stg = sb + (uint32_t)(s % NSTAGE) * STAGE_SZ;
#pragma unroll
        for (int kk = 0; kk < 2; kk++) {
            const uint32_t g0 = gb + (uint32_t)(kk * 4);
            const uint32_t g2 = g0 + 2;
            float2 v0 = lds_f2(stg + arow1 + ((g0 ^ xr) << 4) + aib);
            float2 v1 = lds_f2(stg + arow2 + ((g0 ^ xr) << 4) + aib);
            float2 v2 = lds_f2(stg + arow1 + ((g2 ^ xr) << 4) + aib);
            float2 v3 = lds_f2(stg + arow2 + ((g2 ^ xr) << 4) + aib);
            uint32_t ah[4], al[4];
            ah[0] = split2(v0, al[0]);
            ah[1] = split2(v1, al[1]);
            ah[2] = split2(v2, al[2]);
            ah[3] = split2(v3, al[3]);
            const uint32_t bH = stg + boff + (uint32_t)(kk * 32);
#pragma unroll
            for (int j = 0; j < 4; j++) {
                const uint32_t bo = bH + (uint32_t)(j * 8 * ROWB);
                uint32_t bh0 = lds32(bo);
                uint32_t bh1 = lds32(bo + 16);
                uint32_t bl0 = lds32(bo + BH_SZ);
                uint32_t bl1 = lds32(bo + BH_SZ + 16);
                mma_bf16(acc[j], ah, bh0, bh1);
                mma_bf16(acc[j], al, bh0, bh1);
                mma_bf16(acc[j], ah, bl0, bl1);
            }
        }

        if ((s & 31) == 31) {      // unit complete -> flush partials
            const int u = s >> 5;
            const int m = u >> 4, kc = u & 15;
            float* pp = g_part + ((size_t)kc << 19);
            const int gr0 = m * BM + w * 16 + (lane >> 2);
            const int gr1 = gr0 + 8;
#pragma unroll
            for (int j = 0; j < 4; j++) {
                const int c = j * 8 + (lane & 3) * 2;
                *reinterpret_cast<float2*>(pp + (size_t)gr0 * F_DIM + c) =
                    make_float2(acc[j][0], acc[j][1]);
                *reinterpret_cast<float2*>(pp + (size_t)gr1 * F_DIM + c) =
                    make_float2(acc[j][2], acc[j][3]);
                acc[j][0] = acc[j][1] = acc[j][2] = acc[j][3] = 0.f;
            }
        }
    }
}

// ---------- reduce partials -> diag scale -> split -> g_bh2/g_bl2 (transposed) ----------
__global__ void reduce_split_kernel(const float* __restrict__ diag) {
    __shared__ unsigned short sh[F_DIM][33], sl[F_DIM][33];
    const int tid = threadIdx.x;
    const int r0 = blockIdx.x * 32;
    const int rl = tid >> 3;
    const int c4 = (tid & 7) * 4;
    const int r = r0 + rl;
    float4 acc = *reinterpret_cast<const float4*>(g_part + (size_t)r * F_DIM + c4);
#pragma unroll
    for (int kc = 1; kc < KCHUNKS; kc++) {
        float4 v = *reinterpret_cast<const float4*>(
            g_part + ((size_t)kc << 19) + (size_t)r * F_DIM + c4);
        acc.x += v.x; acc.y += v.y; acc.z += v.z; acc.w += v.w;
    }
    const float d = diag[r];
    float vv[4] = {acc.x * d, acc.y * d, acc.z * d, acc.w * d};
#pragma unroll
    for (int i = 0; i < 4; i++) {
        __nv_bfloat16 h = __float2bfloat16(vv[i]);
        __nv_bfloat16 l = __float2bfloat16(vv[i] - __bfloat162float(h));
        sh[c4 + i][rl] = __bfloat16_as_ushort(h);
        sl[c4 + i][rl] = __bfloat16_as_ushort(l);
    }
    __syncthreads();
    const int cc = tid >> 3;
    const int rr = (tid & 7) * 4;
    ushort4 oh = make_ushort4(sh[cc][rr], sh[cc][rr+1], sh[cc][rr+2], sh[cc][rr+3]);
    ushort4 ol = make_ushort4(sl[cc][rr], sl[cc][rr+1], sl[cc][rr+2], sl[cc][rr+3]);
    *reinterpret_cast<ushort4*>(&g_bh2[(size_t)cc * N_DIM + r0 + rr]) = oh;
    *reinterpret_cast<ushort4*>(&g_bl2[(size_t)cc * N_DIM + r0 + rr]) = ol;
}

// ---------- reduce partials -> f32 out ----------
__global__ void reduce_out_kernel(float* __restrict__ out) {
    const int idx = blockIdx.x * blockDim.x + threadIdx.x;
    float4 acc = *reinterpret_cast<const float4*>(g_part + (size_t)idx * 4);
#pragma unroll
    for (int kc = 1; kc < KCHUNKS; kc++) {
        float4 v = *reinterpret_cast<const float4*>(
            g_part + ((size_t)kc << 19) + (size_t)idx * 4);
        acc.x += v.x; acc.y += v.y; acc.z += v.z; acc.w += v.w;
    }
    *reinterpret_cast<float4*>(out + (size_t)idx * 4) = acc;
}

extern "C" void kernel_launch(void* const* d_in, const int* in_sizes, int n_in,
                              void* d_out, int out_size) {
    const float* feat = (const float*)d_in[0];  // [16384, 32]
    const float* wav  = (const float*)d_in[1];  // [16384, 16384]
    const float* wavi = (const float*)d_in[2];  // [16384, 16384]
    const float* diag = (const float*)d_in[3];  // [16384]
    const float* Wm   = (const float*)d_in[4];  // [32, 32]
    float* out = (float*)d_out;

    cudaFuncSetAttribute(big_gemm_mma<1>, cudaFuncAttributeMaxDynamicSharedMemorySize, SMEM_TOTAL);
    cudaFuncSetAttribute(big_gemm_mma<2>, cudaFuncAttributeMaxDynamicSharedMemorySize, SMEM_TOTAL);

    feat_w_kernel<<<N_DIM / 128, 128>>>(feat, Wm);
    big_gemm_mma<1><<<GRID, THREADS, SMEM_TOTAL>>>(wavi);
    reduce_split_kernel<<<N_DIM / 32, 256>>>(diag);
    big_gemm_mma<2><<<GRID, THREADS, SMEM_TOTAL>>>(wav);
    reduce_out_kernel<<<(N_DIM * F_DIM / 4) / 256, 256>>>(out);
}